// round 12
// baseline (speedup 1.0000x reference)
#include <cuda_runtime.h>
#include <math.h>

#define NN 8192
#define KK 32
#define DD 64
#define DID 32
#define BSZ 4
#define TT 8
#define DSCAN 1024

#define NT 8            // nodes per block
#define ROWS 32         // NT * BSZ rows per block
#define RPA 36          // A pitch (16B-aligned rows, conflict-spread)
#define RPB 36          // B pitch

typedef unsigned long long ull;

// Persistent state (allocation-free scratch)
__device__ float g_h[BSZ * NN * DD];
__device__ float g_msgs[2][BSZ * NN * DD];
__device__ float g_wc[BSZ * NN * KK];
__device__ float g_ident[NN * DID];
__device__ float g_dw2p[256 * 64];    // dw2 cols 0..63 (w_new, decay, ident 0..30)
__device__ float g_dw2c[256];         // dw2 col 64 (ident 31)
__device__ float g_db2p[64];
__device__ float g_db2c;
// k-interleaved layer-1 weights: [k/2][col][2]
__device__ float g_dw1i[256 * 256];
__device__ float g_sw1i[224 * 256];
__device__ float g_mw1i[96 * 256];

__device__ __forceinline__ float sigf(float x) { return 1.0f / (1.0f + __expf(-x)); }

__device__ __forceinline__ ull ffma2(ull a, ull b, ull c) {
    ull d;
    asm("fma.rn.f32x2 %0, %1, %2, %3;" : "=l"(d) : "l"(a), "l"(b), "l"(c));
    return d;
}
__device__ __forceinline__ ull pack2(float x) {
    ull p;
    unsigned u = __float_as_uint(x);
    asm("mov.b64 %0, {%1, %2};" : "=l"(p) : "r"(u), "r"(u));
    return p;
}
__device__ __forceinline__ float2 unpack2(ull p) {
    unsigned lo, hi;
    asm("mov.b64 {%0, %1}, %2;" : "=r"(lo), "=r"(hi) : "l"(p));
    return make_float2(__uint_as_float(lo), __uint_as_float(hi));
}
__device__ __forceinline__ ull repack(float x, float y) {
    ull p;
    unsigned a = __float_as_uint(x), b = __float_as_uint(y);
    asm("mov.b64 %0, {%1, %2};" : "=l"(p) : "r"(a), "r"(b));
    return p;
}

// Interleaved-k CPT=4 segment: LEN2 k-pairs; wsi pre-offset by c0*2.
// Per pair: 2 contiguous LDG.128 cover 4 cols x 2 k-rows.
template <int LEN2, int PITCH>
__device__ __forceinline__ void gemm_seg4i(const float* xs,
                                           const float* __restrict__ wsi,
                                           ull (&acc)[4][4]) {
#pragma unroll 2
    for (int i = 0; i < LEN2; i++) {
        ulonglong2 xe0 = *reinterpret_cast<const ulonglong2*>(xs + (2 * i) * PITCH);
        ulonglong2 xe1 = *reinterpret_cast<const ulonglong2*>(xs + (2 * i) * PITCH + 4);
        ulonglong2 xo0 = *reinterpret_cast<const ulonglong2*>(xs + (2 * i + 1) * PITCH);
        ulonglong2 xo1 = *reinterpret_cast<const ulonglong2*>(xs + (2 * i + 1) * PITCH + 4);
        ull xe[4] = {xe0.x, xe0.y, xe1.x, xe1.y};
        ull xo[4] = {xo0.x, xo0.y, xo1.x, xo1.y};
        const float* wr = wsi + (size_t)i * 512;
        float4 fa = __ldg(reinterpret_cast<const float4*>(wr));
        float4 fb = __ldg(reinterpret_cast<const float4*>(wr) + 1);
        // fa = {w[e][c0], w[o][c0], w[e][c0+1], w[o][c0+1]}, fb same for c0+2/3
        ull we[4] = {pack2(fa.x), pack2(fa.z), pack2(fb.x), pack2(fb.z)};
        ull wo[4] = {pack2(fa.y), pack2(fa.w), pack2(fb.y), pack2(fb.w)};
#pragma unroll
        for (int p = 0; p < 4; p++)
#pragma unroll
            for (int j = 0; j < 4; j++)
                acc[p][j] = ffma2(xe[p], we[j], acc[p][j]);
#pragma unroll
        for (int p = 0; p < 4; p++)
#pragma unroll
            for (int j = 0; j < 4; j++)
                acc[p][j] = ffma2(xo[p], wo[j], acc[p][j]);
    }
}

// Segmented interleaved CPT=4 GEMM (COLS=256), up to 4 (base,len) segments
// (lens in k-rows, all even). 8 warps x 32 cols; rows packed f32x2.
template <int ACT, int IPITCH, int OPITCH,
          int B0, int L0, int B1, int L1, int B2, int L2, int B3, int L3>
__device__ __forceinline__ void gemmS4i(const float* Xt, const float* __restrict__ Wi,
                                        const float* __restrict__ bias, float* Yt) {
    const int w = threadIdx.x >> 5;
    const int lane = threadIdx.x & 31;
    const int r0 = (lane >> 3) * 8;
    const int c0 = w * 32 + (lane & 7) * 4;
    ull acc[4][4];
#pragma unroll
    for (int p = 0; p < 4; p++)
#pragma unroll
        for (int j = 0; j < 4; j++) acc[p][j] = 0ull;

    const float* xb = Xt + r0;
    const float* wb = Wi + 2 * c0;
    gemm_seg4i<L0 / 2, IPITCH>(xb + B0 * IPITCH, wb, acc);
    if (L1 > 0) gemm_seg4i<L1 / 2, IPITCH>(xb + B1 * IPITCH, wb + (size_t)L0 * 256, acc);
    if (L2 > 0) gemm_seg4i<L2 / 2, IPITCH>(xb + B2 * IPITCH, wb + (size_t)(L0 + L1) * 256, acc);
    if (L3 > 0) gemm_seg4i<L3 / 2, IPITCH>(xb + B3 * IPITCH, wb + (size_t)(L0 + L1 + L2) * 256, acc);

#pragma unroll
    for (int j = 0; j < 4; j++) {
        float bc = __ldg(bias + c0 + j);
#pragma unroll
        for (int p = 0; p < 4; p++) {
            float2 v = unpack2(acc[p][j]);
            v.x += bc; v.y += bc;
            if (ACT == 1) {
                v.x = v.x * (1.0f / (1.0f + __expf(-v.x)));
                v.y = v.y * (1.0f / (1.0f + __expf(-v.y)));
            }
            *reinterpret_cast<ull*>(Yt + (c0 + j) * OPITCH + r0 + 2 * p) =
                repack(v.x, v.y);
        }
    }
}

// Plain CPT<=2 k-segment (for layer-2 GEMMs).
template <int CPT, int LEN, int COLS, int UNR, int PITCH>
__device__ __forceinline__ void gemm_seg(const float* xs,
                                         const float* __restrict__ ws,
                                         ull (&acc)[4][CPT]) {
#pragma unroll UNR
    for (int i = 0; i < LEN; i++) {
        ulonglong2 xq0 = *reinterpret_cast<const ulonglong2*>(xs + i * PITCH);
        ulonglong2 xq1 = *reinterpret_cast<const ulonglong2*>(xs + i * PITCH + 4);
        ull xp[4] = {xq0.x, xq0.y, xq1.x, xq1.y};
        float wv[CPT];
        const float* wr = ws + (size_t)i * COLS;
        if (CPT == 2) {
            float2 f = __ldg(reinterpret_cast<const float2*>(wr));
            wv[0] = f.x; wv[1] = f.y;
        } else {
            wv[0] = __ldg(wr);
        }
        ull wp[CPT];
#pragma unroll
        for (int j = 0; j < CPT; j++) wp[j] = pack2(wv[j]);
#pragma unroll
        for (int p = 0; p < 4; p++)
#pragma unroll
            for (int j = 0; j < CPT; j++)
                acc[p][j] = ffma2(xp[p], wp[j], acc[p][j]);
    }
}

// Layer-2 GEMM (single segment), small COLS.
template <int CPT, int ACT, int COLS, int UNR, bool WSYNC, int IPITCH, int OPITCH>
__device__ __forceinline__ void gemmS(const float* Xt, const float* __restrict__ W,
                                      const float* __restrict__ bias,
                                      float* Yt, int yoff) {
    const int w = threadIdx.x >> 5;
    const int lane = threadIdx.x & 31;
    const int r0 = (lane >> 3) * 8;
    const int c0 = w * (COLS / 8) + (lane & 7) * CPT;
    ull acc[4][CPT];
#pragma unroll
    for (int p = 0; p < 4; p++)
#pragma unroll
        for (int j = 0; j < CPT; j++) acc[p][j] = 0ull;

    gemm_seg<CPT, 256, COLS, UNR, IPITCH>(Xt + r0, W + c0, acc);

    if (WSYNC) __syncthreads();

#pragma unroll
    for (int j = 0; j < CPT; j++) {
        float bc = __ldg(bias + c0 + j);
#pragma unroll
        for (int p = 0; p < 4; p++) {
            float2 v = unpack2(acc[p][j]);
            v.x += bc; v.y += bc;
            if (ACT == 1) {
                v.x = v.x * (1.0f / (1.0f + __expf(-v.x)));
                v.y = v.y * (1.0f / (1.0f + __expf(-v.y)));
            } else if (ACT == 2) {
                v.x = tanhf(v.x);
                v.y = tanhf(v.y);
            }
            *reinterpret_cast<ull*>(Yt + (yoff + c0 + j) * OPITCH + r0 + 2 * p) =
                repack(v.x, v.y);
        }
    }
}

// msg layer 2: CPT=1, tanh, reads B, writes g_msgs directly from registers.
__device__ __forceinline__ void gemm_msg2(const float* Bt, const float* __restrict__ W,
                                          const float* __restrict__ bias,
                                          float* __restrict__ gm, int n0) {
    const int w = threadIdx.x >> 5;
    const int lane = threadIdx.x & 31;
    const int r0 = (lane >> 3) * 8;
    const int c0 = w * 8 + (lane & 7);
    ull acc[4][1];
#pragma unroll
    for (int p = 0; p < 4; p++) acc[p][0] = 0ull;
    gemm_seg<1, 256, 64, 8, RPB>(Bt + r0, W + c0, acc);
    float bc = __ldg(bias + c0);
#pragma unroll
    for (int p = 0; p < 4; p++) {
        float2 v = unpack2(acc[p][0]);
        v.x = tanhf(v.x + bc);
        v.y = tanhf(v.y + bc);
        int r = r0 + 2 * p;
        gm[((size_t)(r & 3) * NN + n0 + (r >> 2)) * DD + c0] = v.x;
        gm[((size_t)((r + 1) & 3) * NN + n0 + ((r + 1) >> 2)) * DD + c0] = v.y;
    }
}

__global__ void __launch_bounds__(256, 3) step_kernel(
    const float* __restrict__ cc, const float* __restrict__ hebb,
    const int* __restrict__ conn,
    const float* __restrict__ sb1, const float* __restrict__ sw2,
    const float* __restrict__ sb2,
    const float* __restrict__ mb1, const float* __restrict__ mw2,
    const float* __restrict__ mb2, const float* __restrict__ db1,
    float* __restrict__ out, int t, int p) {
    extern __shared__ float sm[];
    float* A = sm;                     // 256*RPA transposed activations
    float* B = A + 256 * RPA;          // 256*RPB hidden / layer-2 out (in-place)
    float* dec = B + 256 * RPB;        // ROWS decay
    float* xsc = dec + ROWS;           // 32 floats: mod_out col 64
    // transient (dead after gather, overwritten by mod layer1 output):
    float* wk = B;                     // ROWS*KK sigmoid(w_conn)
    int* idxs = (int*)(B + ROWS * KK); // NT*KK neighbor indices

    const int tid = threadIdx.x;
    const int n0 = blockIdx.x * NT;

    // ---- Phase 0: indices + sigmoid(w_conn) + transposed mod_in fills ----
    // A rows: [0:32] hebbian, [32:96] h, [96:128] ident, [128:192] received,
    //         [192:256] inject
    {
        int ln = tid >> 5, k = tid & 31;
        idxs[tid] = conn[(n0 + ln) * KK + k];
    }
    for (int i = tid; i < ROWS * KK; i += 256) {
        int r = i >> 5, k = i & 31, ln = r >> 2, b = r & 3;
        wk[i] = sigf(g_wc[((size_t)b * NN + n0 + ln) * KK + k]);
    }
    for (int i = tid; i < ROWS * KK; i += 256) {
        int r = i >> 5, j = i & 31, ln = r >> 2, b = r & 3;
        A[j * RPA + r] = hebb[((size_t)b * NN + n0 + ln) * KK + j];
    }
    for (int i = tid; i < ROWS * DD; i += 256) {
        int r = i >> 6, d = i & 63, ln = r >> 2, b = r & 3;
        A[(32 + d) * RPA + r] = g_h[((size_t)b * NN + n0 + ln) * DD + d];
    }
    for (int i = tid; i < ROWS * DID; i += 256) {
        int r = i >> 5, j = i & 31, ln = r >> 2;
        A[(96 + j) * RPA + r] = g_ident[(n0 + ln) * DID + j];
    }
    for (int i = tid; i < ROWS * DD; i += 256) {
        int r = i >> 6, d = i & 63, ln = r >> 2, b = r & 3;
        int n = n0 + ln;
        A[(192 + d) * RPA + r] = cc[((size_t)b * TT + t) * DSCAN + (n >> 9) * DD + d];
    }
    __syncthreads();

    // ---- received = sum_k sigmoid(w) * msgs[neighbor] -> A rows [128:192] ----
    {
        const float* mp = g_msgs[p];
#pragma unroll
        for (int task = tid; task < 512; task += 256) {
            int r = task >> 4;
            int q = task & 15;
            int ln = r >> 2, b = r & 3;
            const float* wrow = wk + r * KK;
            const int* irow = idxs + ln * KK;
            const float* mb = mp + (size_t)b * NN * DD + 4 * q;
            float4 acc = make_float4(0.f, 0.f, 0.f, 0.f);
#pragma unroll 16
            for (int k = 0; k < KK; k++) {
                float wv = wrow[k];
                int nb = irow[k];
                float4 m = __ldcg(reinterpret_cast<const float4*>(mb + (size_t)nb * DD));
                acc.x = fmaf(wv, m.x, acc.x);
                acc.y = fmaf(wv, m.y, acc.y);
                acc.z = fmaf(wv, m.z, acc.z);
                acc.w = fmaf(wv, m.w, acc.w);
            }
            float* dst = A + (128 + 4 * q) * RPA + r;
            dst[0] = acc.x;
            dst[RPA] = acc.y;
            dst[2 * RPA] = acc.z;
            dst[3 * RPA] = acc.w;
        }
    }
    __syncthreads();

    // ---- mod MLP layer1: A[0:256] -> B (silu), interleaved weights ----
    gemmS4i<1, RPA, RPB, 0, 256, 0, 0, 0, 0, 0, 0>(A, g_dw1i, db1, B);
    __syncthreads();

    // ---- mod layer2 extra column (dw2 col 64 = ident delta 31): GEMV ----
    {
        int r = tid >> 3, j = tid & 7;
        float acc = 0.0f;
#pragma unroll 8
        for (int kk = 0; kk < 32; kk++) {
            int k = j * 32 + ((kk + j) & 31);
            acc = fmaf(B[k * RPB + r], __ldg(g_dw2c + k), acc);
        }
        acc += __shfl_down_sync(0xffffffffu, acc, 4);
        acc += __shfl_down_sync(0xffffffffu, acc, 2);
        acc += __shfl_down_sync(0xffffffffu, acc, 1);
        if (j == 0) xsc[r] = acc + g_db2c;
    }

    // ---- mod layer2 main: B[0:256] -> B rows [0:64) in-place (WSYNC) ----
    gemmS<1, 0, 64, 8, true, RPB, RPB>(B, g_dw2p, g_db2p, B, 0);
    __syncthreads();

    // ---- w_new, decay, identity update; ide2 -> A rows [96:128] ----
    for (int i = tid; i < ROWS * KK; i += 256) {
        int r = i >> 5, k = i & 31, ln = r >> 2, b = r & 3;
        g_wc[((size_t)b * NN + n0 + ln) * KK + k] = B[k * RPB + r];
    }
    if (tid < ROWS) dec[tid] = sigf(B[32 * RPB + tid]);
    {
        int ln = tid >> 5, j = tid & 31;
        float s;
        if (j < 31) {
            const float* cr = B + (33 + j) * RPB + ln * 4;
            s = cr[0] + cr[1] + cr[2] + cr[3];
        } else {
            s = xsc[ln * 4] + xsc[ln * 4 + 1] + xsc[ln * 4 + 2] + xsc[ln * 4 + 3];
        }
        float v = g_ident[(n0 + ln) * DID + j] + 0.25f * s;
        g_ident[(n0 + ln) * DID + j] = v;
        float* ar = A + (96 + j) * RPA + ln * 4;
        ar[0] = v; ar[1] = v; ar[2] = v; ar[3] = v;
    }
    __syncthreads();

    // ---- state MLP layer1: segments [received,inject,h,ide2] of A -> B ----
    gemmS4i<1, RPA, RPB, 128, 64, 192, 64, 32, 64, 96, 32>(A, g_sw1i, sb1, B);
    __syncthreads();
    gemmS<1, 2, 64, 8, false, RPB, RPA>(B, sw2, sb2, A, 128);  // tanh -> A[128:192]
    __syncthreads();

    // ---- h_new = decay*h + (1-decay)*tanh -> A rows [192:256], g_h, out ----
    for (int i = tid; i < ROWS * DD; i += 256) {
        int r = i >> 6, d = i & 63, ln = r >> 2, b = r & 3;
        float de = dec[r];
        float hn = de * A[(32 + d) * RPA + r] + (1.0f - de) * A[(128 + d) * RPA + r];
        g_h[((size_t)b * NN + n0 + ln) * DD + d] = hn;
        out[(((size_t)b * TT + t) * NN + n0 + ln) * DD + d] = hn;
        A[(192 + d) * RPA + r] = hn;
    }
    __syncthreads();

    // ---- msg MLP: layer1 reads [h_new, ide2]; layer2 writes g_msgs direct ----
    gemmS4i<1, RPA, RPB, 192, 64, 96, 32, 0, 0, 0, 0>(A, g_mw1i, mb1, B);
    __syncthreads();
    gemm_msg2(B, mw2, mb2, g_msgs[p ^ 1], n0);
}

__global__ void init_kernel(const float* __restrict__ h0, const float* __restrict__ m0,
                            const float* __restrict__ w0, const float* __restrict__ id0,
                            const float* __restrict__ dw2, const float* __restrict__ db2,
                            const float* __restrict__ dw1, const float* __restrict__ sw1,
                            const float* __restrict__ mw1) {
    size_t i = (size_t)blockIdx.x * blockDim.x + threadIdx.x;
    if (i < (size_t)BSZ * NN * DD) {
        g_h[i] = h0[i];
        g_msgs[0][i] = m0[i];
    }
    if (i < (size_t)BSZ * NN * KK) g_wc[i] = w0[i];
    if (i < (size_t)NN * DID) g_ident[i] = id0[i];
    if (i < 256 * 64) {
        int r = (int)i >> 6, c = (int)i & 63;
        g_dw2p[i] = dw2[r * 65 + c];
    }
    if (i < 256) g_dw2c[i] = dw2[i * 65 + 64];
    if (i < 64) g_db2p[i] = db2[i];
    if (i == 0) g_db2c = db2[64];
    // interleave layer-1 weights: [k][c] -> [k/2][c][2]
    if (i < 256 * 256) {
        int k = (int)i >> 8, c = (int)i & 255;
        g_dw1i[(((size_t)(k >> 1) * 256) + c) * 2 + (k & 1)] = dw1[i];
    }
    if (i < 224 * 256) {
        int k = (int)i >> 8, c = (int)i & 255;
        g_sw1i[(((size_t)(k >> 1) * 256) + c) * 2 + (k & 1)] = sw1[i];
    }
    if (i < 96 * 256) {
        int k = (int)i >> 8, c = (int)i & 255;
        g_mw1i[(((size_t)(k >> 1) * 256) + c) * 2 + (k & 1)] = mw1[i];
    }
}

#define SMEM_BYTES ((256 * RPA + 256 * RPB + ROWS + 32) * 4)

extern "C" void kernel_launch(void* const* d_in, const int* in_sizes, int n_in,
                              void* d_out, int out_size) {
    const float* cc   = (const float*)d_in[0];
    const float* h0   = (const float*)d_in[1];
    const float* m0   = (const float*)d_in[2];
    const float* w0   = (const float*)d_in[3];
    const float* hebb = (const float*)d_in[4];
    const float* id0  = (const float*)d_in[5];
    const float* sw1  = (const float*)d_in[6];
    const float* sb1  = (const float*)d_in[7];
    const float* sw2  = (const float*)d_in[8];
    const float* sb2  = (const float*)d_in[9];
    const float* mw1  = (const float*)d_in[10];
    const float* mb1  = (const float*)d_in[11];
    const float* mw2  = (const float*)d_in[12];
    const float* mb2  = (const float*)d_in[13];
    const float* dw1  = (const float*)d_in[14];
    const float* db1  = (const float*)d_in[15];
    const float* dw2  = (const float*)d_in[16];
    const float* db2  = (const float*)d_in[17];
    const int* conn   = (const int*)d_in[18];
    float* out = (float*)d_out;

    cudaFuncSetAttribute(step_kernel, cudaFuncAttributeMaxDynamicSharedMemorySize,
                         SMEM_BYTES);

    init_kernel<<<(BSZ * NN * DD + 255) / 256, 256>>>(h0, m0, w0, id0, dw2, db2,
                                                      dw1, sw1, mw1);
    for (int t = 0; t < TT; t++) {
        step_kernel<<<NN / NT, 256, SMEM_BYTES>>>(
            cc, hebb, conn, sb1, sw2, sb2, mb1, mw2, mb2,
            db1, out, t, t & 1);
    }
}

// round 14
// speedup vs baseline: 1.0336x; 1.0336x over previous
#include <cuda_runtime.h>
#include <math.h>

#define NN 8192
#define KK 32
#define DD 64
#define DID 32
#define BSZ 4
#define TT 8
#define DSCAN 1024

#define NT 8            // nodes per block
#define ROWS 32         // NT * BSZ rows per block
#define RPA 36          // A pitch (16B-aligned rows, conflict-spread)
#define RPB 36          // B pitch

typedef unsigned long long ull;

// Persistent state (allocation-free scratch)
__device__ float g_h[BSZ * NN * DD];
__device__ float g_msgs[2][BSZ * NN * DD];
__device__ float g_wc[BSZ * NN * KK];
__device__ float g_ident[NN * DID];
// Duplicated {w,w} layer-2 weights (row = 2*64 floats)
__device__ float g_dw2d[256 * 128];   // dw2 cols 0..63 (w_new, decay, ident 0..30)
__device__ float g_sw2d[256 * 128];
__device__ float g_mw2d[256 * 128];
__device__ float g_dw2c[256];         // dw2 col 64 (ident delta 31)
__device__ float g_db2p[64];
__device__ float g_db2c;

__device__ __forceinline__ float sigf(float x) { return 1.0f / (1.0f + __expf(-x)); }

__device__ __forceinline__ ull ffma2(ull a, ull b, ull c) {
    ull d;
    asm("fma.rn.f32x2 %0, %1, %2, %3;" : "=l"(d) : "l"(a), "l"(b), "l"(c));
    return d;
}
__device__ __forceinline__ ull pack2(float x) {
    ull p;
    unsigned u = __float_as_uint(x);
    asm("mov.b64 %0, {%1, %2};" : "=l"(p) : "r"(u), "r"(u));
    return p;
}
__device__ __forceinline__ float2 unpack2(ull p) {
    unsigned lo, hi;
    asm("mov.b64 {%0, %1}, %2;" : "=r"(lo), "=r"(hi) : "l"(p));
    return make_float2(__uint_as_float(lo), __uint_as_float(hi));
}
__device__ __forceinline__ ull repack(float x, float y) {
    ull p;
    unsigned a = __float_as_uint(x), b = __float_as_uint(y);
    asm("mov.b64 %0, {%1, %2};" : "=l"(p) : "r"(a), "r"(b));
    return p;
}

// One contiguous k-segment: LEN rows of X starting at xs (pitch PITCH). CPT=4.
template <int LEN, int UNR, int PITCH>
__device__ __forceinline__ void gemm_seg4(const float* xs,
                                          const float* __restrict__ ws,
                                          ull (&acc)[4][4]) {
#pragma unroll UNR
    for (int i = 0; i < LEN; i++) {
        ulonglong2 xq0 = *reinterpret_cast<const ulonglong2*>(xs + i * PITCH);
        ulonglong2 xq1 = *reinterpret_cast<const ulonglong2*>(xs + i * PITCH + 4);
        ull xp[4] = {xq0.x, xq0.y, xq1.x, xq1.y};
        float4 f = __ldg(reinterpret_cast<const float4*>(ws + (size_t)i * 256));
        ull wp[4] = {pack2(f.x), pack2(f.y), pack2(f.z), pack2(f.w)};
#pragma unroll
        for (int p = 0; p < 4; p++)
#pragma unroll
            for (int j = 0; j < 4; j++)
                acc[p][j] = ffma2(xp[p], wp[j], acc[p][j]);
    }
}

// Dup-weight CPT=1 k-segment: wsd points into a {w,w}-duplicated matrix
// (row stride 128 floats), pre-offset by 2*c0.
template <int LEN, int UNR, int PITCH>
__device__ __forceinline__ void gemm_seg_dup1(const float* xs,
                                              const float* __restrict__ wsd,
                                              ull (&acc)[4]) {
#pragma unroll UNR
    for (int i = 0; i < LEN; i++) {
        ulonglong2 xq0 = *reinterpret_cast<const ulonglong2*>(xs + i * PITCH);
        ulonglong2 xq1 = *reinterpret_cast<const ulonglong2*>(xs + i * PITCH + 4);
        ull wp = __ldg(reinterpret_cast<const ull*>(wsd + (size_t)i * 128));
        acc[0] = ffma2(xq0.x, wp, acc[0]);
        acc[1] = ffma2(xq0.y, wp, acc[1]);
        acc[2] = ffma2(xq1.x, wp, acc[2]);
        acc[3] = ffma2(xq1.y, wp, acc[3]);
    }
}

// Segmented CPT=4 GEMM (COLS=256) over up to 4 compile-time (base,len) segments.
// 8 warps x 32 cols; lane = 4 row-groups x 8 col-groups; rows packed f32x2.
template <int ACT, int UNR, int IPITCH, int OPITCH,
          int B0, int L0, int B1, int L1, int B2, int L2, int B3, int L3>
__device__ __forceinline__ void gemmS4(const float* Xt, const float* __restrict__ W,
                                       const float* __restrict__ bias, float* Yt) {
    const int w = threadIdx.x >> 5;
    const int lane = threadIdx.x & 31;
    const int r0 = (lane >> 3) * 8;
    const int c0 = w * 32 + (lane & 7) * 4;
    ull acc[4][4];
#pragma unroll
    for (int p = 0; p < 4; p++)
#pragma unroll
        for (int j = 0; j < 4; j++) acc[p][j] = 0ull;

    const float* xb = Xt + r0;
    const float* wb = W + c0;
    gemm_seg4<L0, UNR, IPITCH>(xb + B0 * IPITCH, wb, acc);
    if (L1 > 0) gemm_seg4<L1, UNR, IPITCH>(xb + B1 * IPITCH, wb + (size_t)L0 * 256, acc);
    if (L2 > 0) gemm_seg4<L2, UNR, IPITCH>(xb + B2 * IPITCH, wb + (size_t)(L0 + L1) * 256, acc);
    if (L3 > 0) gemm_seg4<L3, UNR, IPITCH>(xb + B3 * IPITCH, wb + (size_t)(L0 + L1 + L2) * 256, acc);

#pragma unroll
    for (int j = 0; j < 4; j++) {
        float bc = __ldg(bias + c0 + j);
#pragma unroll
        for (int p = 0; p < 4; p++) {
            float2 v = unpack2(acc[p][j]);
            v.x += bc; v.y += bc;
            if (ACT == 1) {
                v.x = v.x * (1.0f / (1.0f + __expf(-v.x)));
                v.y = v.y * (1.0f / (1.0f + __expf(-v.y)));
            }
            *reinterpret_cast<ull*>(Yt + (c0 + j) * OPITCH + r0 + 2 * p) =
                repack(v.x, v.y);
        }
    }
}

// Layer-2 GEMM (CPT=1, COLS=64, dup weights, single 256-k segment).
// ACT: 0 = none, 2 = tanh. WSYNC: barrier before in-place writeback.
template <int ACT, bool WSYNC, int IPITCH, int OPITCH>
__device__ __forceinline__ void gemmD(const float* Xt, const float* __restrict__ Wd,
                                      const float* __restrict__ bias,
                                      float* Yt, int yoff) {
    const int w = threadIdx.x >> 5;
    const int lane = threadIdx.x & 31;
    const int r0 = (lane >> 3) * 8;
    const int c0 = w * 8 + (lane & 7);
    ull acc[4] = {0ull, 0ull, 0ull, 0ull};
    gemm_seg_dup1<256, 8, IPITCH>(Xt + r0, Wd + 2 * c0, acc);

    if (WSYNC) __syncthreads();

    float bc = __ldg(bias + c0);
#pragma unroll
    for (int p = 0; p < 4; p++) {
        float2 v = unpack2(acc[p]);
        v.x += bc; v.y += bc;
        if (ACT == 2) {
            v.x = tanhf(v.x);
            v.y = tanhf(v.y);
        }
        *reinterpret_cast<ull*>(Yt + (yoff + c0) * OPITCH + r0 + 2 * p) =
            repack(v.x, v.y);
    }
}

// msg layer 2: CPT=1, dup weights, tanh, writes g_msgs directly from registers.
__device__ __forceinline__ void gemm_msg2(const float* Bt, const float* __restrict__ Wd,
                                          const float* __restrict__ bias,
                                          float* __restrict__ gm, int n0) {
    const int w = threadIdx.x >> 5;
    const int lane = threadIdx.x & 31;
    const int r0 = (lane >> 3) * 8;
    const int c0 = w * 8 + (lane & 7);
    ull acc[4] = {0ull, 0ull, 0ull, 0ull};
    gemm_seg_dup1<256, 8, RPB>(Bt + r0, Wd + 2 * c0, acc);
    float bc = __ldg(bias + c0);
#pragma unroll
    for (int p = 0; p < 4; p++) {
        float2 v = unpack2(acc[p]);
        v.x = tanhf(v.x + bc);
        v.y = tanhf(v.y + bc);
        int r = r0 + 2 * p;
        gm[((size_t)(r & 3) * NN + n0 + (r >> 2)) * DD + c0] = v.x;
        gm[((size_t)((r + 1) & 3) * NN + n0 + ((r + 1) >> 2)) * DD + c0] = v.y;
    }
}

__global__ void __launch_bounds__(256, 3) step_kernel(
    const float* __restrict__ cc, const float* __restrict__ hebb,
    const int* __restrict__ conn,
    const float* __restrict__ sw1, const float* __restrict__ sb1,
    const float* __restrict__ sb2,
    const float* __restrict__ mw1, const float* __restrict__ mb1,
    const float* __restrict__ mb2,
    const float* __restrict__ dw1, const float* __restrict__ db1,
    float* __restrict__ out, int t, int p) {
    extern __shared__ float sm[];
    float* A = sm;                     // 256*RPA transposed activations
    float* B = A + 256 * RPA;          // 256*RPB hidden / layer-2 out (in-place)
    float* dec = B + 256 * RPB;        // ROWS decay
    float* xsc = dec + ROWS;           // 32 floats: mod_out col 64
    // transient (dead after gather, overwritten by mod layer1 output):
    float* wk = B;                     // ROWS*KK sigmoid(w_conn)
    int* idxs = (int*)(B + ROWS * KK); // NT*KK neighbor indices

    const int tid = threadIdx.x;
    const int n0 = blockIdx.x * NT;

    // ---- Phase 0: indices + sigmoid(w_conn) + transposed mod_in fills ----
    // A rows: [0:32] hebbian, [32:96] h, [96:128] ident, [128:192] received,
    //         [192:256] inject
    {
        int ln = tid >> 5, k = tid & 31;
        idxs[tid] = conn[(n0 + ln) * KK + k];
    }
    for (int i = tid; i < ROWS * KK; i += 256) {
        int r = i >> 5, k = i & 31, ln = r >> 2, b = r & 3;
        wk[i] = sigf(g_wc[((size_t)b * NN + n0 + ln) * KK + k]);
    }
    for (int i = tid; i < ROWS * KK; i += 256) {
        int r = i >> 5, j = i & 31, ln = r >> 2, b = r & 3;
        A[j * RPA + r] = hebb[((size_t)b * NN + n0 + ln) * KK + j];
    }
    for (int i = tid; i < ROWS * DD; i += 256) {
        int r = i >> 6, d = i & 63, ln = r >> 2, b = r & 3;
        A[(32 + d) * RPA + r] = g_h[((size_t)b * NN + n0 + ln) * DD + d];
    }
    for (int i = tid; i < ROWS * DID; i += 256) {
        int r = i >> 5, j = i & 31, ln = r >> 2;
        A[(96 + j) * RPA + r] = g_ident[(n0 + ln) * DID + j];
    }
    for (int i = tid; i < ROWS * DD; i += 256) {
        int r = i >> 6, d = i & 63, ln = r >> 2, b = r & 3;
        int n = n0 + ln;
        A[(192 + d) * RPA + r] = cc[((size_t)b * TT + t) * DSCAN + (n >> 9) * DD + d];
    }
    __syncthreads();

    // ---- received = sum_k sigmoid(w) * msgs[neighbor] -> A rows [128:192] ----
    {
        const float* mp = g_msgs[p];
#pragma unroll
        for (int task = tid; task < 512; task += 256) {
            int r = task >> 4;
            int q = task & 15;
            int ln = r >> 2, b = r & 3;
            const float* wrow = wk + r * KK;
            const int* irow = idxs + ln * KK;
            const float* mb = mp + (size_t)b * NN * DD + 4 * q;
            float4 acc = make_float4(0.f, 0.f, 0.f, 0.f);
#pragma unroll 8
            for (int k = 0; k < KK; k++) {
                float wv = wrow[k];
                int nb = irow[k];
                float4 m = __ldcg(reinterpret_cast<const float4*>(mb + (size_t)nb * DD));
                acc.x = fmaf(wv, m.x, acc.x);
                acc.y = fmaf(wv, m.y, acc.y);
                acc.z = fmaf(wv, m.z, acc.z);
                acc.w = fmaf(wv, m.w, acc.w);
            }
            float* dst = A + (128 + 4 * q) * RPA + r;
            dst[0] = acc.x;
            dst[RPA] = acc.y;
            dst[2 * RPA] = acc.z;
            dst[3 * RPA] = acc.w;
        }
    }
    __syncthreads();

    // ---- mod MLP layer1: A[0:256] -> B (silu) ----
    gemmS4<1, 4, RPA, RPB, 0, 256, 0, 0, 0, 0, 0, 0>(A, dw1, db1, B);
    __syncthreads();

    // ---- mod layer2 extra column (dw2 col 64 = ident delta 31): GEMV ----
    {
        int r = tid >> 3, j = tid & 7;
        float acc = 0.0f;
#pragma unroll 8
        for (int kk = 0; kk < 32; kk++) {
            int k = j * 32 + ((kk + j) & 31);
            acc = fmaf(B[k * RPB + r], __ldg(g_dw2c + k), acc);
        }
        acc += __shfl_down_sync(0xffffffffu, acc, 4);
        acc += __shfl_down_sync(0xffffffffu, acc, 2);
        acc += __shfl_down_sync(0xffffffffu, acc, 1);
        if (j == 0) xsc[r] = acc + g_db2c;
    }

    // ---- mod layer2 main: B[0:256] -> B rows [0:64) in-place (WSYNC) ----
    gemmD<0, true, RPB, RPB>(B, g_dw2d, g_db2p, B, 0);
    __syncthreads();

    // ---- w_new, decay, identity update; ide2 -> A rows [96:128] ----
    for (int i = tid; i < ROWS * KK; i += 256) {
        int r = i >> 5, k = i & 31, ln = r >> 2, b = r & 3;
        g_wc[((size_t)b * NN + n0 + ln) * KK + k] = B[k * RPB + r];
    }
    if (tid < ROWS) dec[tid] = sigf(B[32 * RPB + tid]);
    {
        int ln = tid >> 5, j = tid & 31;
        float s;
        if (j < 31) {
            const float* cr = B + (33 + j) * RPB + ln * 4;
            s = cr[0] + cr[1] + cr[2] + cr[3];
        } else {
            s = xsc[ln * 4] + xsc[ln * 4 + 1] + xsc[ln * 4 + 2] + xsc[ln * 4 + 3];
        }
        float v = g_ident[(n0 + ln) * DID + j] + 0.25f * s;
        g_ident[(n0 + ln) * DID + j] = v;
        float* ar = A + (96 + j) * RPA + ln * 4;
        ar[0] = v; ar[1] = v; ar[2] = v; ar[3] = v;
    }
    __syncthreads();

    // ---- state MLP layer1: segments [received,inject,h,ide2] of A -> B ----
    gemmS4<1, 4, RPA, RPB, 128, 64, 192, 64, 32, 64, 96, 32>(A, sw1, sb1, B);
    __syncthreads();
    gemmD<2, false, RPB, RPA>(B, g_sw2d, sb2, A, 128);  // tanh -> A[128:192]
    __syncthreads();

    // ---- h_new = decay*h + (1-decay)*tanh -> A rows [192:256], g_h, out ----
    for (int i = tid; i < ROWS * DD; i += 256) {
        int r = i >> 6, d = i & 63, ln = r >> 2, b = r & 3;
        float de = dec[r];
        float hn = de * A[(32 + d) * RPA + r] + (1.0f - de) * A[(128 + d) * RPA + r];
        g_h[((size_t)b * NN + n0 + ln) * DD + d] = hn;
        out[(((size_t)b * TT + t) * NN + n0 + ln) * DD + d] = hn;
        A[(192 + d) * RPA + r] = hn;
    }
    __syncthreads();

    // ---- msg MLP: layer1 reads [h_new, ide2]; layer2 writes g_msgs direct ----
    gemmS4<1, 4, RPA, RPB, 192, 64, 96, 32, 0, 0, 0, 0>(A, mw1, mb1, B);
    __syncthreads();
    gemm_msg2(B, g_mw2d, mb2, g_msgs[p ^ 1], n0);
}

__global__ void init_kernel(const float* __restrict__ h0, const float* __restrict__ m0,
                            const float* __restrict__ w0, const float* __restrict__ id0,
                            const float* __restrict__ dw2, const float* __restrict__ db2,
                            const float* __restrict__ sw2, const float* __restrict__ mw2) {
    size_t i = (size_t)blockIdx.x * blockDim.x + threadIdx.x;
    if (i < (size_t)BSZ * NN * DD) {
        g_h[i] = h0[i];
        g_msgs[0][i] = m0[i];
    }
    if (i < (size_t)BSZ * NN * KK) g_wc[i] = w0[i];
    if (i < (size_t)NN * DID) g_ident[i] = id0[i];
    if (i < 256 * 64) {
        int r = (int)i >> 6, c = (int)i & 63;
        float v = dw2[r * 65 + c];
        g_dw2d[r * 128 + 2 * c] = v;
        g_dw2d[r * 128 + 2 * c + 1] = v;
        float v2 = sw2[i];
        g_sw2d[r * 128 + 2 * c] = v2;
        g_sw2d[r * 128 + 2 * c + 1] = v2;
        float v3 = mw2[i];
        g_mw2d[r * 128 + 2 * c] = v3;
        g_mw2d[r * 128 + 2 * c + 1] = v3;
    }
    if (i < 256) g_dw2c[i] = dw2[i * 65 + 64];
    if (i < 64) g_db2p[i] = db2[i];
    if (i == 0) g_db2c = db2[64];
}

#define SMEM_BYTES ((256 * RPA + 256 * RPB + ROWS + 32) * 4)

extern "C" void kernel_launch(void* const* d_in, const int* in_sizes, int n_in,
                              void* d_out, int out_size) {
    const float* cc   = (const float*)d_in[0];
    const float* h0   = (const float*)d_in[1];
    const float* m0   = (const float*)d_in[2];
    const float* w0   = (const float*)d_in[3];
    const float* hebb = (const float*)d_in[4];
    const float* id0  = (const float*)d_in[5];
    const float* sw1  = (const float*)d_in[6];
    const float* sb1  = (const float*)d_in[7];
    const float* sw2  = (const float*)d_in[8];
    const float* sb2  = (const float*)d_in[9];
    const float* mw1  = (const float*)d_in[10];
    const float* mb1  = (const float*)d_in[11];
    const float* mw2  = (const float*)d_in[12];
    const float* mb2  = (const float*)d_in[13];
    const float* dw1  = (const float*)d_in[14];
    const float* db1  = (const float*)d_in[15];
    const float* dw2  = (const float*)d_in[16];
    const float* db2  = (const float*)d_in[17];
    const int* conn   = (const int*)d_in[18];
    float* out = (float*)d_out;

    cudaFuncSetAttribute(step_kernel, cudaFuncAttributeMaxDynamicSharedMemorySize,
                         SMEM_BYTES);

    init_kernel<<<(BSZ * NN * DD + 255) / 256, 256>>>(h0, m0, w0, id0, dw2, db2,
                                                      sw2, mw2);
    for (int t = 0; t < TT; t++) {
        step_kernel<<<NN / NT, 256, SMEM_BYTES>>>(
            cc, hebb, conn, sw1, sb1, sb2, mw1, mb1, mb2,
            dw1, db1, out, t, t & 1);
    }
}

// round 15
// speedup vs baseline: 1.0611x; 1.0265x over previous
#include <cuda_runtime.h>
#include <math.h>

#define NN 8192
#define KK 32
#define DD 64
#define DID 32
#define BSZ 4
#define TT 8
#define DSCAN 1024

#define NT 8            // nodes per block
#define ROWS 32         // NT * BSZ rows per block
#define RPA 36          // A pitch (16B-aligned rows, conflict-spread)
#define RPB 36          // B pitch

typedef unsigned long long ull;

// Persistent state (allocation-free scratch)
__device__ float g_h[BSZ * NN * DD];
__device__ float g_msgs[2][BSZ * NN * DD];
__device__ float g_wc[BSZ * NN * KK];
__device__ float g_ident[NN * DID];
__device__ float g_dw2p[256 * 64];    // dw2 cols 0..63 (w_new, decay, ident 0..30)
__device__ float g_dw2c[256];         // dw2 col 64 (ident 31)
__device__ float g_db2p[64];
__device__ float g_db2c;

__device__ __forceinline__ float sigf(float x) { return 1.0f / (1.0f + __expf(-x)); }

__device__ __forceinline__ ull ffma2(ull a, ull b, ull c) {
    ull d;
    asm("fma.rn.f32x2 %0, %1, %2, %3;" : "=l"(d) : "l"(a), "l"(b), "l"(c));
    return d;
}
__device__ __forceinline__ ull pack2(float x) {
    ull p;
    unsigned u = __float_as_uint(x);
    asm("mov.b64 %0, {%1, %2};" : "=l"(p) : "r"(u), "r"(u));
    return p;
}
__device__ __forceinline__ float2 unpack2(ull p) {
    unsigned lo, hi;
    asm("mov.b64 {%0, %1}, %2;" : "=r"(lo), "=r"(hi) : "l"(p));
    return make_float2(__uint_as_float(lo), __uint_as_float(hi));
}
__device__ __forceinline__ ull repack(float x, float y) {
    ull p;
    unsigned a = __float_as_uint(x), b = __float_as_uint(y);
    asm("mov.b64 %0, {%1, %2};" : "=l"(p) : "r"(a), "r"(b));
    return p;
}

// One contiguous k-segment: LEN rows of X starting at xs (pitch PITCH).
template <int CPT, int LEN, int COLS, int UNR, int PITCH>
__device__ __forceinline__ void gemm_seg(const float* xs,
                                         const float* __restrict__ ws,
                                         ull (&acc)[4][CPT]) {
#pragma unroll UNR
    for (int i = 0; i < LEN; i++) {
        ulonglong2 xq0 = *reinterpret_cast<const ulonglong2*>(xs + i * PITCH);
        ulonglong2 xq1 = *reinterpret_cast<const ulonglong2*>(xs + i * PITCH + 4);
        ull xp[4] = {xq0.x, xq0.y, xq1.x, xq1.y};
        float wv[CPT];
        const float* wr = ws + (size_t)i * COLS;
        if (CPT == 4) {
            float4 f = __ldg(reinterpret_cast<const float4*>(wr));
            wv[0] = f.x; wv[1] = f.y; wv[2] = f.z; wv[3] = f.w;
        } else if (CPT == 2) {
            float2 f = __ldg(reinterpret_cast<const float2*>(wr));
            wv[0] = f.x; wv[1] = f.y;
        } else {
            wv[0] = __ldg(wr);
        }
        ull wp[CPT];
#pragma unroll
        for (int j = 0; j < CPT; j++) wp[j] = pack2(wv[j]);
#pragma unroll
        for (int p = 0; p < 4; p++)
#pragma unroll
            for (int j = 0; j < CPT; j++)
                acc[p][j] = ffma2(xp[p], wp[j], acc[p][j]);
    }
}

// Segmented GEMM over up to 4 compile-time (base,len) row segments.
// 8 warps split COLS; lane = 4 row-groups x 8 col-groups; rows packed f32x2.
template <int CPT, int ACT, int COLS, int UNR, bool WSYNC, int IPITCH, int OPITCH,
          int B0, int L0, int B1, int L1, int B2, int L2, int B3, int L3>
__device__ __forceinline__ void gemmS(const float* Xt, const float* __restrict__ W,
                                      const float* __restrict__ bias,
                                      float* Yt, int yoff) {
    const int w = threadIdx.x >> 5;
    const int lane = threadIdx.x & 31;
    const int r0 = (lane >> 3) * 8;
    const int c0 = w * (COLS / 8) + (lane & 7) * CPT;
    ull acc[4][CPT];
#pragma unroll
    for (int p = 0; p < 4; p++)
#pragma unroll
        for (int j = 0; j < CPT; j++) acc[p][j] = 0ull;

    const float* xb = Xt + r0;
    const float* wb = W + c0;
    gemm_seg<CPT, L0, COLS, UNR, IPITCH>(xb + B0 * IPITCH, wb, acc);
    if (L1 > 0) gemm_seg<CPT, L1, COLS, UNR, IPITCH>(xb + B1 * IPITCH, wb + (size_t)L0 * COLS, acc);
    if (L2 > 0) gemm_seg<CPT, L2, COLS, UNR, IPITCH>(xb + B2 * IPITCH, wb + (size_t)(L0 + L1) * COLS, acc);
    if (L3 > 0) gemm_seg<CPT, L3, COLS, UNR, IPITCH>(xb + B3 * IPITCH, wb + (size_t)(L0 + L1 + L2) * COLS, acc);

    if (WSYNC) __syncthreads();

#pragma unroll
    for (int j = 0; j < CPT; j++) {
        float bc = __ldg(bias + c0 + j);
#pragma unroll
        for (int p = 0; p < 4; p++) {
            float2 v = unpack2(acc[p][j]);
            v.x += bc; v.y += bc;
            if (ACT == 1) {
                v.x = v.x * (1.0f / (1.0f + __expf(-v.x)));
                v.y = v.y * (1.0f / (1.0f + __expf(-v.y)));
            } else if (ACT == 2) {
                v.x = tanhf(v.x);
                v.y = tanhf(v.y);
            }
            *reinterpret_cast<ull*>(Yt + (yoff + c0 + j) * OPITCH + r0 + 2 * p) =
                repack(v.x, v.y);
        }
    }
}

// msg layer 2: CPT=1, tanh, reads B, writes g_msgs directly from registers.
__device__ __forceinline__ void gemm_msg2(const float* Bt, const float* __restrict__ W,
                                          const float* __restrict__ bias,
                                          float* __restrict__ gm, int n0) {
    const int w = threadIdx.x >> 5;
    const int lane = threadIdx.x & 31;
    const int r0 = (lane >> 3) * 8;
    const int c0 = w * 8 + (lane & 7);
    ull acc[4][1];
#pragma unroll
    for (int p = 0; p < 4; p++) acc[p][0] = 0ull;
    gemm_seg<1, 256, 64, 8, RPB>(Bt + r0, W + c0, acc);
    float bc = __ldg(bias + c0);
#pragma unroll
    for (int p = 0; p < 4; p++) {
        float2 v = unpack2(acc[p][0]);
        v.x = tanhf(v.x + bc);
        v.y = tanhf(v.y + bc);
        int r = r0 + 2 * p;
        gm[((size_t)(r & 3) * NN + n0 + (r >> 2)) * DD + c0] = v.x;
        gm[((size_t)((r + 1) & 3) * NN + n0 + ((r + 1) >> 2)) * DD + c0] = v.y;
    }
}

__global__ void __launch_bounds__(256, 3) step_kernel(
    const float* __restrict__ cc, const float* __restrict__ hebb,
    const int* __restrict__ conn,
    const float* __restrict__ sw1, const float* __restrict__ sb1,
    const float* __restrict__ sw2, const float* __restrict__ sb2,
    const float* __restrict__ mw1, const float* __restrict__ mb1,
    const float* __restrict__ mw2, const float* __restrict__ mb2,
    const float* __restrict__ dw1, const float* __restrict__ db1,
    float* __restrict__ out, int t, int p) {
    extern __shared__ float sm[];
    float* A = sm;                     // 256*RPA transposed activations
    float* B = A + 256 * RPA;          // 256*RPB hidden / layer-2 out (in-place)
    float* dec = B + 256 * RPB;        // ROWS decay
    float* xsc = dec + ROWS;           // 32 floats: mod_out col 64
    // transient (dead after gather, overwritten by mod layer1 output):
    float* wk = B;                     // ROWS*KK sigmoid(w_conn)
    int* idxs = (int*)(B + ROWS * KK); // NT*KK neighbor indices

    const int tid = threadIdx.x;
    const int n0 = blockIdx.x * NT;

    // ---- Phase 0: indices + sigmoid(w_conn) + transposed mod_in fills ----
    // A rows: [0:32] hebbian, [32:96] h, [96:128] ident, [128:192] received,
    //         [192:256] inject
    {
        int ln = tid >> 5, k = tid & 31;
        idxs[tid] = conn[(n0 + ln) * KK + k];
    }
    for (int i = tid; i < ROWS * KK; i += 256) {
        int r = i >> 5, k = i & 31, ln = r >> 2, b = r & 3;
        wk[i] = sigf(g_wc[((size_t)b * NN + n0 + ln) * KK + k]);
    }
    for (int i = tid; i < ROWS * KK; i += 256) {
        int r = i >> 5, j = i & 31, ln = r >> 2, b = r & 3;
        A[j * RPA + r] = hebb[((size_t)b * NN + n0 + ln) * KK + j];
    }
    for (int i = tid; i < ROWS * DD; i += 256) {
        int r = i >> 6, d = i & 63, ln = r >> 2, b = r & 3;
        A[(32 + d) * RPA + r] = g_h[((size_t)b * NN + n0 + ln) * DD + d];
    }
    for (int i = tid; i < ROWS * DID; i += 256) {
        int r = i >> 5, j = i & 31, ln = r >> 2;
        A[(96 + j) * RPA + r] = g_ident[(n0 + ln) * DID + j];
    }
    for (int i = tid; i < ROWS * DD; i += 256) {
        int r = i >> 6, d = i & 63, ln = r >> 2, b = r & 3;
        int n = n0 + ln;
        A[(192 + d) * RPA + r] = cc[((size_t)b * TT + t) * DSCAN + (n >> 9) * DD + d];
    }
    __syncthreads();

    // ---- received = sum_k sigmoid(w) * msgs[neighbor] -> A rows [128:192] ----
    {
        const float* mp = g_msgs[p];
#pragma unroll
        for (int task = tid; task < 512; task += 256) {
            int r = task >> 4;
            int q = task & 15;
            int ln = r >> 2, b = r & 3;
            const float* wrow = wk + r * KK;
            const int* irow = idxs + ln * KK;
            const float* mb = mp + (size_t)b * NN * DD + 4 * q;
            float4 acc = make_float4(0.f, 0.f, 0.f, 0.f);
#pragma unroll 8
            for (int k = 0; k < KK; k++) {
                float wv = wrow[k];
                int nb = irow[k];
                float4 m = __ldcg(reinterpret_cast<const float4*>(mb + (size_t)nb * DD));
                acc.x = fmaf(wv, m.x, acc.x);
                acc.y = fmaf(wv, m.y, acc.y);
                acc.z = fmaf(wv, m.z, acc.z);
                acc.w = fmaf(wv, m.w, acc.w);
            }
            float* dst = A + (128 + 4 * q) * RPA + r;
            dst[0] = acc.x;
            dst[RPA] = acc.y;
            dst[2 * RPA] = acc.z;
            dst[3 * RPA] = acc.w;
        }
    }
    __syncthreads();

    // ---- mod MLP layer1: A[0:256] -> B (silu) ----
    gemmS<4, 1, 256, 8, false, RPA, RPB,
          0, 256, 0, 0, 0, 0, 0, 0>(A, dw1, db1, B, 0);
    __syncthreads();

    // ---- mod layer2 extra column (dw2 col 64 = ident delta 31): GEMV ----
    {
        int r = tid >> 3, j = tid & 7;
        float acc = 0.0f;
#pragma unroll 8
        for (int kk = 0; kk < 32; kk++) {
            int k = j * 32 + ((kk + j) & 31);
            acc = fmaf(B[k * RPB + r], __ldg(g_dw2c + k), acc);
        }
        acc += __shfl_down_sync(0xffffffffu, acc, 4);
        acc += __shfl_down_sync(0xffffffffu, acc, 2);
        acc += __shfl_down_sync(0xffffffffu, acc, 1);
        if (j == 0) xsc[r] = acc + g_db2c;
    }

    // ---- mod layer2 main: B[0:256] -> B rows [0:64) in-place (WSYNC) ----
    gemmS<1, 0, 64, 8, true, RPB, RPB,
          0, 256, 0, 0, 0, 0, 0, 0>(B, g_dw2p, g_db2p, B, 0);
    __syncthreads();

    // ---- w_new, decay, identity update; ide2 -> A rows [96:128] ----
    for (int i = tid; i < ROWS * KK; i += 256) {
        int r = i >> 5, k = i & 31, ln = r >> 2, b = r & 3;
        g_wc[((size_t)b * NN + n0 + ln) * KK + k] = B[k * RPB + r];
    }
    if (tid < ROWS) dec[tid] = sigf(B[32 * RPB + tid]);
    {
        int ln = tid >> 5, j = tid & 31;
        float s;
        if (j < 31) {
            const float* cr = B + (33 + j) * RPB + ln * 4;
            s = cr[0] + cr[1] + cr[2] + cr[3];
        } else {
            s = xsc[ln * 4] + xsc[ln * 4 + 1] + xsc[ln * 4 + 2] + xsc[ln * 4 + 3];
        }
        float v = g_ident[(n0 + ln) * DID + j] + 0.25f * s;
        g_ident[(n0 + ln) * DID + j] = v;
        float* ar = A + (96 + j) * RPA + ln * 4;
        ar[0] = v; ar[1] = v; ar[2] = v; ar[3] = v;
    }
    __syncthreads();

    // ---- state MLP layer1: segments [received,inject,h,ide2] of A -> B ----
    gemmS<4, 1, 256, 8, false, RPA, RPB,
          128, 64, 192, 64, 32, 64, 96, 32>(A, sw1, sb1, B, 0);
    __syncthreads();
    gemmS<1, 2, 64, 8, false, RPB, RPA,
          0, 256, 0, 0, 0, 0, 0, 0>(B, sw2, sb2, A, 128);  // tanh -> A[128:192]
    __syncthreads();

    // ---- h_new = decay*h + (1-decay)*tanh -> A rows [192:256], g_h, out ----
    for (int i = tid; i < ROWS * DD; i += 256) {
        int r = i >> 6, d = i & 63, ln = r >> 2, b = r & 3;
        float de = dec[r];
        float hn = de * A[(32 + d) * RPA + r] + (1.0f - de) * A[(128 + d) * RPA + r];
        g_h[((size_t)b * NN + n0 + ln) * DD + d] = hn;
        out[(((size_t)b * TT + t) * NN + n0 + ln) * DD + d] = hn;
        A[(192 + d) * RPA + r] = hn;
    }
    __syncthreads();

    // ---- msg MLP: layer1 reads [h_new, ide2]; layer2 writes g_msgs direct ----
    gemmS<4, 1, 256, 8, false, RPA, RPB,
          192, 64, 96, 32, 0, 0, 0, 0>(A, mw1, mb1, B, 0);
    __syncthreads();
    gemm_msg2(B, mw2, mb2, g_msgs[p ^ 1], n0);
}

__global__ void init_kernel(const float* __restrict__ h0, const float* __restrict__ m0,
                            const float* __restrict__ w0, const float* __restrict__ id0,
                            const float* __restrict__ dw2, const float* __restrict__ db2) {
    size_t i = (size_t)blockIdx.x * blockDim.x + threadIdx.x;
    if (i < (size_t)BSZ * NN * DD) {
        g_h[i] = h0[i];
        g_msgs[0][i] = m0[i];
    }
    if (i < (size_t)BSZ * NN * KK) g_wc[i] = w0[i];
    if (i < (size_t)NN * DID) g_ident[i] = id0[i];
    if (i < 256 * 64) {
        int r = (int)i >> 6, c = (int)i & 63;
        g_dw2p[i] = dw2[r * 65 + c];
    }
    if (i < 256) g_dw2c[i] = dw2[i * 65 + 64];
    if (i < 64) g_db2p[i] = db2[i];
    if (i == 0) g_db2c = db2[64];
}

#define SMEM_BYTES ((256 * RPA + 256 * RPB + ROWS + 32) * 4)

extern "C" void kernel_launch(void* const* d_in, const int* in_sizes, int n_in,
                              void* d_out, int out_size) {
    const float* cc   = (const float*)d_in[0];
    const float* h0   = (const float*)d_in[1];
    const float* m0   = (const float*)d_in[2];
    const float* w0   = (const float*)d_in[3];
    const float* hebb = (const float*)d_in[4];
    const float* id0  = (const float*)d_in[5];
    const float* sw1  = (const float*)d_in[6];
    const float* sb1  = (const float*)d_in[7];
    const float* sw2  = (const float*)d_in[8];
    const float* sb2  = (const float*)d_in[9];
    const float* mw1  = (const float*)d_in[10];
    const float* mb1  = (const float*)d_in[11];
    const float* mw2  = (const float*)d_in[12];
    const float* mb2  = (const float*)d_in[13];
    const float* dw1  = (const float*)d_in[14];
    const float* db1  = (const float*)d_in[15];
    const float* dw2  = (const float*)d_in[16];
    const float* db2  = (const float*)d_in[17];
    const int* conn   = (const int*)d_in[18];
    float* out = (float*)d_out;

    cudaFuncSetAttribute(step_kernel, cudaFuncAttributeMaxDynamicSharedMemorySize,
                         SMEM_BYTES);

    init_kernel<<<(BSZ * NN * DD + 255) / 256, 256>>>(h0, m0, w0, id0, dw2, db2);
    for (int t = 0; t < TT; t++) {
        step_kernel<<<NN / NT, 256, SMEM_BYTES>>>(
            cc, hebb, conn, sw1, sb1, sw2, sb2, mw1, mb1, mw2, mb2,
            dw1, db1, out, t, t & 1);
    }
}